// round 6
// baseline (speedup 1.0000x reference)
#include <cuda_runtime.h>

// ----------------------------------------------------------------------------
// MaskedMSA: x@Wqkv+b -> (faithful reshape) -> causal MHA -> sa@Wout+b
// B=4, S=2048, E=1024, HIDDEN=1024, HEADS=16, d_head=64
//
// Reshape semantics (row-major):
//   qkv[b] is [2048,3072] flat; head h, pos s, chan c  ->  flat h*393216 + s*192 + c
//   q = c in [0,64), k = [64,128), v = [128,192)
//   sa: head h, pos s, dim d -> flat h*131072 + s*64 + d  into [2048,1024]
// ----------------------------------------------------------------------------

#define B_  4
#define S_  2048
#define E_  1024
#define H3  3072
#define NH  16
#define CH  192   // 3*64 channels per head-local position

typedef unsigned long long ull;

// scratch (no cudaMalloc allowed)
__device__ float g_qkv[B_ * S_ * H3];  // 96 MB
__device__ float g_sa [B_ * S_ * E_]; // 32 MB

// ---------------- packed fp32x2 helpers (exact fp32 math, 2x issue density) --
__device__ __forceinline__ void fma2(ull& d, ull a, ull b) {
    asm("fma.rn.f32x2 %0, %1, %2, %0;" : "+l"(d) : "l"(a), "l"(b));
}
__device__ __forceinline__ void mul2(ull& d, ull a, ull b) {
    asm("mul.rn.f32x2 %0, %1, %2;" : "=l"(d) : "l"(a), "l"(b));
}
__device__ __forceinline__ ull pack2(float x, float y) {
    ull r; asm("mov.b64 %0, {%1, %2};" : "=l"(r) : "f"(x), "f"(y)); return r;
}
__device__ __forceinline__ ull bcast2(float x) { return pack2(x, x); }
__device__ __forceinline__ void unpack2(ull v, float& x, float& y) {
    asm("mov.b64 {%0, %1}, %2;" : "=f"(x), "=f"(y) : "l"(v));
}

// ----------------------------------------------------------------------------
// SGEMM with bias: C[M,N] = A[M,K] @ Bw[K,N] + bias[N]
// 128x128 block tile, BK=8, 256 threads, 8x8 micro-tile as 8x4 f32x2 accums.
// M%128==0, N%128==0, K%8==0 (holds for all three GEMM shapes here).
// ----------------------------------------------------------------------------
__global__ __launch_bounds__(256)
void gemm_bias_kernel(const float* __restrict__ A, const float* __restrict__ Bw,
                      const float* __restrict__ bias, float* __restrict__ C,
                      int M, int N, int K)
{
    __shared__ __align__(16) float As[8][128];   // transposed A tile
    __shared__ __align__(16) float Bs[8][128];

    const int t  = threadIdx.x;
    const int tx = t & 15;          // 0..15 -> N direction (8 cols)
    const int ty = t >> 4;          // 0..15 -> M direction (8 rows)
    const int bm = blockIdx.y * 128;
    const int bn = blockIdx.x * 128;

    // staging load indices
    const int arow = t >> 1;              // 0..127
    const int acol = (t & 1) * 4;         // 0 or 4
    const int brow = t >> 5;              // 0..7
    const int bcol = (t & 31) * 4;        // 0..124

    const float* Ap = A + (bm + arow) * K + acol;
    const float* Bp = Bw + brow * N + bn + bcol;

    float4 aF = *(const float4*)Ap;
    float4 bF = *(const float4*)Bp;

    ull acc[8][4];
#pragma unroll
    for (int i = 0; i < 8; i++)
#pragma unroll
        for (int j = 0; j < 4; j++) acc[i][j] = 0ull;

    for (int k0 = 0; k0 < K; k0 += 8) {
        // stage into SMEM
        As[acol + 0][arow] = aF.x;
        As[acol + 1][arow] = aF.y;
        As[acol + 2][arow] = aF.z;
        As[acol + 3][arow] = aF.w;
        *(float4*)&Bs[brow][bcol] = bF;
        __syncthreads();

        // prefetch next k-slab while computing this one
        if (k0 + 8 < K) {
            aF = *(const float4*)(Ap + k0 + 8);
            bF = *(const float4*)(Bp + (k0 + 8) * N);
        }

#pragma unroll
        for (int k = 0; k < 8; k++) {
            float4 a0 = *(const float4*)&As[k][ty * 8];
            float4 a1 = *(const float4*)&As[k][ty * 8 + 4];
            const ull* bp = (const ull*)&Bs[k][tx * 8];
            ull b0 = bp[0], b1 = bp[1], b2 = bp[2], b3 = bp[3];
            float av[8] = {a0.x, a0.y, a0.z, a0.w, a1.x, a1.y, a1.z, a1.w};
#pragma unroll
            for (int i = 0; i < 8; i++) {
                ull ai = bcast2(av[i]);
                fma2(acc[i][0], ai, b0);
                fma2(acc[i][1], ai, b1);
                fma2(acc[i][2], ai, b2);
                fma2(acc[i][3], ai, b3);
            }
        }
        __syncthreads();
    }

    // epilogue: add bias, store
#pragma unroll
    for (int i = 0; i < 8; i++) {
        const int row = bm + ty * 8 + i;
        float* crow = C + row * N + bn + tx * 8;
#pragma unroll
        for (int j = 0; j < 4; j++) {
            float x0, x1; unpack2(acc[i][j], x0, x1);
            const int col = bn + tx * 8 + 2 * j;
            float2 o; o.x = x0 + bias[col]; o.y = x1 + bias[col + 1];
            *(float2*)(crow + 2 * j) = o;
        }
    }
}

// ----------------------------------------------------------------------------
// Causal flash attention over the reshaped Q/K/V views.
// Block: 128 threads = 128 query rows (one q-tile). grid = (16 qtiles, 64 b*h).
// K-tiles of 32 columns; Ks stored d-major, Vs j-major -> inner-loop SMEM
// reads are warp-uniform broadcasts (conflict-free).
// Dynamic SMEM: Qs 128x65 + Ks 64x32 + Vs 32x64 = 49664 B.
// ----------------------------------------------------------------------------
#define LDQ 65
#define ATTN_SMEM ((128 * LDQ + 64 * 32 + 32 * 64) * 4)

__global__ __launch_bounds__(128)
void attn_kernel()
{
    extern __shared__ __align__(16) float sh[];
    float* Qs = sh;                       // [128][65]
    float* Ks = sh + 128 * LDQ;           // [64][32]  (d-major)
    float* Vs = Ks + 64 * 32;             // [32][64]  (j-major)

    const int t  = threadIdx.x;
    const int qi = (int)gridDim.x - 1 - (int)blockIdx.x;  // heavy tiles first
    const int bh = blockIdx.y;
    const int b  = bh >> 4;
    const int h  = bh & 15;

    const float* base = g_qkv + b * (S_ * H3) + h * (S_ * CH);
    const int r = qi * 128 + t;           // head-local query row

    // load own q row into SMEM (pre-scaled)
    const float scale = rsqrtf(2048.0f);  // (2*HIDDEN)^-0.5
    {
        const float* qrow = base + r * CH;
#pragma unroll
        for (int i = 0; i < 16; i++) {
            float4 v4 = *(const float4*)(qrow + i * 4);
            float* qd = Qs + t * LDQ + i * 4;
            qd[0] = v4.x * scale; qd[1] = v4.y * scale;
            qd[2] = v4.z * scale; qd[3] = v4.w * scale;
        }
    }

    ull o2[32];
#pragma unroll
    for (int i = 0; i < 32; i++) o2[i] = 0ull;
    float m = -1e30f, l = 0.0f;

    const int nkt = 4 * (qi + 1);
    const int jj = t >> 2;                // 0..31  (tile row for K/V loads)
    const int dbase = (t & 3) * 16;       // 0/16/32/48

    for (int kt = 0; kt < nkt; kt++) {
        __syncthreads();
        // cooperative K (transposed) + V (straight) tile loads
        {
            const float* kr = base + (kt * 32 + jj) * CH + 64 + dbase;
            const float* vr = kr + 64;
#pragma unroll
            for (int i = 0; i < 4; i++) {
                float4 kv = *(const float4*)(kr + i * 4);
                const int d = dbase + i * 4;
                Ks[(d + 0) * 32 + jj] = kv.x;
                Ks[(d + 1) * 32 + jj] = kv.y;
                Ks[(d + 2) * 32 + jj] = kv.z;
                Ks[(d + 3) * 32 + jj] = kv.w;
                float4 vv = *(const float4*)(vr + i * 4);
                *(float4*)&Vs[jj * 64 + d] = vv;
            }
        }
        __syncthreads();

        // ---- S = (q . K^T): 32 cols in 16 packed accumulators ----
        ull s2[16];
#pragma unroll
        for (int i = 0; i < 16; i++) s2[i] = 0ull;
        const float* qrowS = Qs + t * LDQ;
#pragma unroll 4
        for (int d = 0; d < 64; d++) {
            ull qq = bcast2(qrowS[d]);
            const ulonglong2* kp = (const ulonglong2*)(Ks + d * 32);
#pragma unroll
            for (int j4 = 0; j4 < 8; j4++) {
                ulonglong2 kk = kp[j4];
                fma2(s2[2 * j4],     qq, kk.x);
                fma2(s2[2 * j4 + 1], qq, kk.y);
            }
        }

        // ---- mask + online softmax ----
        float sv[32];
#pragma unroll
        for (int i = 0; i < 16; i++) unpack2(s2[i], sv[2 * i], sv[2 * i + 1]);
        const int colBase = kt * 32;
        float tmax = -1e30f;
#pragma unroll
        for (int j = 0; j < 32; j++) {
            if (colBase + j > r) sv[j] = -1e30f;
            tmax = fmaxf(tmax, sv[j]);
        }
        const float mnew = fmaxf(m, tmax);
        const float corr = __expf(m - mnew);
        m = mnew;
        float psum = 0.0f;
#pragma unroll
        for (int j = 0; j < 32; j++) {
            sv[j] = __expf(sv[j] - mnew);
            psum += sv[j];
        }
        l = l * corr + psum;
        ull cc = bcast2(corr);
#pragma unroll
        for (int i = 0; i < 32; i++) mul2(o2[i], o2[i], cc);

        // ---- O += P @ V ----
        for (int j = 0; j < 32; j++) {
            ull pp = bcast2(sv[j]);
            const ulonglong2* vp = (const ulonglong2*)(Vs + j * 64);
#pragma unroll
            for (int d4 = 0; d4 < 16; d4++) {
                ulonglong2 vv = vp[d4];
                fma2(o2[2 * d4],     pp, vv.x);
                fma2(o2[2 * d4 + 1], pp, vv.y);
            }
        }
    }

    // normalize + store into the re-scrambled sa layout
    const float invl = 1.0f / l;
    ull ii = bcast2(invl);
#pragma unroll
    for (int i = 0; i < 32; i++) mul2(o2[i], o2[i], ii);

    float* dst = g_sa + b * (S_ * E_) + (h * 128 + (r >> 4)) * E_ + (r & 15) * 64;
#pragma unroll
    for (int d4 = 0; d4 < 16; d4++) {
        ulonglong2 w; w.x = o2[2 * d4]; w.y = o2[2 * d4 + 1];
        *(ulonglong2*)(dst + d4 * 4) = w;
    }
}

// ----------------------------------------------------------------------------
extern "C" void kernel_launch(void* const* d_in, const int* in_sizes, int n_in,
                              void* d_out, int out_size)
{
    const float* x     = (const float*)d_in[0];  // [4,2048,1024]
    const float* W_qkv = (const float*)d_in[1];  // [1024,3072]
    const float* b_qkv = (const float*)d_in[2];  // [3072]
    const float* W_out = (const float*)d_in[3];  // [1024,1024]
    const float* b_out = (const float*)d_in[4];  // [1024]
    float* out = (float*)d_out;                  // [4,2048,1024]

    float* qkv = nullptr;
    float* sa  = nullptr;
    cudaGetSymbolAddress((void**)&qkv, g_qkv);
    cudaGetSymbolAddress((void**)&sa,  g_sa);

    cudaFuncSetAttribute(attn_kernel,
                         cudaFuncAttributeMaxDynamicSharedMemorySize, ATTN_SMEM);

    // 1) QKV projection: [8192,1024] @ [1024,3072] + b
    gemm_bias_kernel<<<dim3(H3 / 128, (B_ * S_) / 128), 256>>>(
        x, W_qkv, b_qkv, qkv, B_ * S_, H3, E_);

    // 2) causal attention per (b,h) over reshaped views
    attn_kernel<<<dim3(16, B_ * NH), 128, ATTN_SMEM>>>();

    // 3) output projection: [8192,1024] @ [1024,1024] + b
    gemm_bias_kernel<<<dim3(E_ / 128, (B_ * S_) / 128), 256>>>(
        sa, W_out, b_out, out, B_ * S_, E_, E_);
}

// round 8
// speedup vs baseline: 1.2438x; 1.2438x over previous
#include <cuda_runtime.h>
#include <cuda_bf16.h>
#include <cstdint>

// ----------------------------------------------------------------------------
// MaskedMSA: x@Wqkv+b -> (faithful reshape) -> causal MHA -> sa@Wout+b
// B=4, S=2048, E=1024, HIDDEN=1024, HEADS=16, d_head=64
// GEMMs on HMMA (mma.sync m16n8k16 bf16) with hi/lo split: 3 passes give
// fp32-like accuracy. (tcgen05 is not reachable: harness PTX target is
// compute_103, not 103a.)
// ----------------------------------------------------------------------------

#define B_  4
#define S_  2048
#define E_  1024
#define H3  3072
#define NH  16
#define CH  192
#define MROWS (B_ * S_)   // 8192

typedef unsigned long long ull;

// ---------------- scratch (no cudaMalloc allowed) ----------------
__device__ float g_qkv[MROWS * H3];                 // 96 MB fp32
__device__ __nv_bfloat16 g_xh[MROWS * E_];          // x hi/lo
__device__ __nv_bfloat16 g_xl[MROWS * E_];
__device__ __nv_bfloat16 g_wqh[H3 * E_];            // W_qkv^T hi/lo  [3072][1024]
__device__ __nv_bfloat16 g_wql[H3 * E_];
__device__ __nv_bfloat16 g_woh[E_ * E_];            // W_out^T hi/lo  [1024][1024]
__device__ __nv_bfloat16 g_wol[E_ * E_];
__device__ __nv_bfloat16 g_sah[MROWS * E_];         // attention out hi/lo
__device__ __nv_bfloat16 g_sal[MROWS * E_];

// ---------------- packed fp32x2 helpers ----------------
__device__ __forceinline__ void fma2(ull& d, ull a, ull b) {
    asm("fma.rn.f32x2 %0, %1, %2, %0;" : "+l"(d) : "l"(a), "l"(b));
}
__device__ __forceinline__ void mul2(ull& d, ull a, ull b) {
    asm("mul.rn.f32x2 %0, %1, %2;" : "=l"(d) : "l"(a), "l"(b));
}
__device__ __forceinline__ ull pack2(float x, float y) {
    ull r; asm("mov.b64 %0, {%1, %2};" : "=l"(r) : "f"(x), "f"(y)); return r;
}
__device__ __forceinline__ ull bcast2(float x) { return pack2(x, x); }
__device__ __forceinline__ void unpack2(ull v, float& x, float& y) {
    asm("mov.b64 {%0, %1}, %2;" : "=f"(x), "=f"(y) : "l"(v));
}

// ---------------- warp-MMA helpers ----------------
__device__ __forceinline__ uint32_t s2u(const void* p) {
    uint32_t a;
    asm("{ .reg .u64 t; cvta.to.shared.u64 t, %1; cvt.u32.u64 %0, t; }" : "=r"(a) : "l"(p));
    return a;
}
__device__ __forceinline__ void ldm_x4(uint32_t* r, uint32_t addr) {
    asm volatile("ldmatrix.sync.aligned.m8n8.x4.shared.b16 {%0,%1,%2,%3}, [%4];"
                 : "=r"(r[0]), "=r"(r[1]), "=r"(r[2]), "=r"(r[3]) : "r"(addr));
}
__device__ __forceinline__ void ldm_x2(uint32_t* r, uint32_t addr) {
    asm volatile("ldmatrix.sync.aligned.m8n8.x2.shared.b16 {%0,%1}, [%2];"
                 : "=r"(r[0]), "=r"(r[1]) : "r"(addr));
}
__device__ __forceinline__ void mma_bf16(float* d, const uint32_t* a, const uint32_t* b) {
    asm volatile("mma.sync.aligned.m16n8k16.row.col.f32.bf16.bf16.f32 "
                 "{%0,%1,%2,%3}, {%4,%5,%6,%7}, {%8,%9}, {%0,%1,%2,%3};"
                 : "+f"(d[0]), "+f"(d[1]), "+f"(d[2]), "+f"(d[3])
                 : "r"(a[0]), "r"(a[1]), "r"(a[2]), "r"(a[3]), "r"(b[0]), "r"(b[1]));
}

// ----------------------------------------------------------------------------
// Conversion kernels
// ----------------------------------------------------------------------------
__global__ void split_kernel(const float* __restrict__ in,
                             __nv_bfloat16* __restrict__ hi,
                             __nv_bfloat16* __restrict__ lo, int n4) {
    int i = blockIdx.x * blockDim.x + threadIdx.x;
    if (i >= n4) return;
    float4 v = ((const float4*)in)[i];
    __nv_bfloat16 h0 = __float2bfloat16(v.x), h1 = __float2bfloat16(v.y);
    __nv_bfloat16 h2 = __float2bfloat16(v.z), h3 = __float2bfloat16(v.w);
    __nv_bfloat16 l0 = __float2bfloat16(v.x - __bfloat162float(h0));
    __nv_bfloat16 l1 = __float2bfloat16(v.y - __bfloat162float(h1));
    __nv_bfloat16 l2 = __float2bfloat16(v.z - __bfloat162float(h2));
    __nv_bfloat16 l3 = __float2bfloat16(v.w - __bfloat162float(h3));
    __nv_bfloat162* H = (__nv_bfloat162*)hi;
    __nv_bfloat162* L = (__nv_bfloat162*)lo;
    H[2 * i]     = __nv_bfloat162(h0, h1);
    H[2 * i + 1] = __nv_bfloat162(h2, h3);
    L[2 * i]     = __nv_bfloat162(l0, l1);
    L[2 * i + 1] = __nv_bfloat162(l2, l3);
}

// W [K,N] fp32 -> Th/Tl [N,K] bf16
__global__ void transpose_split_kernel(const float* __restrict__ W,
                                       __nv_bfloat16* __restrict__ Th,
                                       __nv_bfloat16* __restrict__ Tl,
                                       int K, int N) {
    __shared__ float tile[32][33];
    const int bx = blockIdx.x * 32;   // N direction
    const int by = blockIdx.y * 32;   // K direction
    const int tx = threadIdx.x, ty = threadIdx.y;
#pragma unroll
    for (int i = 0; i < 32; i += 8)
        tile[ty + i][tx] = W[(by + ty + i) * N + bx + tx];
    __syncthreads();
#pragma unroll
    for (int i = 0; i < 32; i += 8) {
        float v = tile[tx][ty + i];
        __nv_bfloat16 h = __float2bfloat16(v);
        int idx = (bx + ty + i) * K + by + tx;
        Th[idx] = h;
        Tl[idx] = __float2bfloat16(v - __bfloat162float(h));
    }
}

// ----------------------------------------------------------------------------
// HMMA GEMM: C[M,N] = Ah@Bh^T + Ah@Bl^T + Al@Bh^T + bias
// A*: [M,K] bf16 row-major.  B*: [N,K] bf16 row-major (= K x N col-major). C fp32.
// 128x128 block tile, BK=32, 256 threads = 8 warps (2M x 4N, 64x32 each).
// SMEM padded stride 40 bf16 -> conflict-free ldmatrix. Double buffered.
// ----------------------------------------------------------------------------
#define GBM 128
#define GBN 128
#define GBK 32
#define LDT 40
#define TBUF (GBM * LDT)     // elements per matrix per buffer

__global__ __launch_bounds__(256)
void gemm_tc_kernel(const __nv_bfloat16* __restrict__ Ah, const __nv_bfloat16* __restrict__ Al,
                    const __nv_bfloat16* __restrict__ Bh, const __nv_bfloat16* __restrict__ Bl,
                    const float* __restrict__ bias, float* __restrict__ C,
                    int M, int N, int K)
{
    __shared__ __align__(16) __nv_bfloat16 sA[2 * TBUF];
    __shared__ __align__(16) __nv_bfloat16 sB[2 * TBUF];

    const int t = threadIdx.x;
    const int lane = t & 31;
    const int warp = t >> 5;
    const int wm = warp & 1;        // 0..1 -> 64-row slab
    const int wn = warp >> 1;       // 0..3 -> 32-col slab
    const int bm = blockIdx.y * GBM, bn = blockIdx.x * GBN;

    // global load mapping: tile is 128 rows x 32 bf16; each thread 2x uint4
    const int lrow = t >> 1;
    const int lhalf = (t & 1) * 16;     // bf16 offset within row

    const uint32_t sAu = s2u(sA);
    const uint32_t sBu = s2u(sB);

    // ldmatrix base offsets (bytes) within a buffer
    const uint32_t aoff = ((uint32_t)(wm * 64 + (lane & 15)) * LDT + (lane >> 4) * 8) * 2;
    const uint32_t boff = ((uint32_t)(wn * 32 + (lane & 7)) * LDT + ((lane >> 3) & 1) * 8) * 2;

    float acc[4][4][4];
#pragma unroll
    for (int mi = 0; mi < 4; mi++)
#pragma unroll
        for (int ni = 0; ni < 4; ni++)
#pragma unroll
            for (int j = 0; j < 4; j++) acc[mi][ni][j] = 0.0f;

    const int nkt = K / GBK;            // 32
    const int ntile = 3 * nkt;          // 96

    // tile -> global pointers (3 precision segments)
    auto aptr = [&](int tl) -> const uint4* {
        const int seg = tl / nkt, kt = tl % nkt;
        const __nv_bfloat16* A = (seg == 2) ? Al : Ah;
        return (const uint4*)(A + (ull)(bm + lrow) * K + kt * GBK + lhalf);
    };
    auto bptr = [&](int tl) -> const uint4* {
        const int seg = tl / nkt, kt = tl % nkt;
        const __nv_bfloat16* Bw = (seg == 1) ? Bl : Bh;
        return (const uint4*)(Bw + (ull)(bn + lrow) * K + kt * GBK + lhalf);
    };

    uint4 pa0, pa1, pb0, pb1;
    { const uint4* p = aptr(0); pa0 = p[0]; pa1 = p[1]; }
    { const uint4* p = bptr(0); pb0 = p[0]; pb1 = p[1]; }

    // store slot for this thread within a buffer
    __nv_bfloat16* stA = sA + lrow * LDT + lhalf;
    __nv_bfloat16* stB = sB + lrow * LDT + lhalf;

    // prologue: fill buffer 0
    *(uint4*)stA = pa0; *(uint4*)(stA + 8) = pa1;
    *(uint4*)stB = pb0; *(uint4*)(stB + 8) = pb1;
    __syncthreads();

    for (int tl = 0; tl < ntile; tl++) {
        const int cur = tl & 1;
        const int nxt = cur ^ 1;

        // issue global prefetch for next tile
        if (tl + 1 < ntile) {
            const uint4* p = aptr(tl + 1); pa0 = p[0]; pa1 = p[1];
            const uint4* q = bptr(tl + 1); pb0 = q[0]; pb1 = q[1];
        }

        // compute current buffer
        const uint32_t aB = sAu + cur * (TBUF * 2) + aoff;
        const uint32_t bB = sBu + cur * (TBUF * 2) + boff;
#pragma unroll
        for (int ks = 0; ks < 2; ks++) {
            uint32_t af[4][4], bf[4][2];
#pragma unroll
            for (int mi = 0; mi < 4; mi++)
                ldm_x4(af[mi], aB + ((uint32_t)mi * 16 * LDT + ks * 16) * 2);
#pragma unroll
            for (int ni = 0; ni < 4; ni++)
                ldm_x2(bf[ni], bB + ((uint32_t)ni * 8 * LDT + ks * 16) * 2);
#pragma unroll
            for (int mi = 0; mi < 4; mi++)
#pragma unroll
                for (int ni = 0; ni < 4; ni++)
                    mma_bf16(acc[mi][ni], af[mi], bf[ni]);
        }

        // stage next tile into the other buffer (safe: last read at tl-1, synced)
        if (tl + 1 < ntile) {
            __nv_bfloat16* dA = stA + nxt * TBUF;
            __nv_bfloat16* dB = stB + nxt * TBUF;
            *(uint4*)dA = pa0; *(uint4*)(dA + 8) = pa1;
            *(uint4*)dB = pb0; *(uint4*)(dB + 8) = pb1;
        }
        __syncthreads();
    }

    // epilogue: bias + store
    const int rbase = bm + wm * 64 + (lane >> 2);
    const int cbase = bn + wn * 32 + (lane & 3) * 2;
#pragma unroll
    for (int mi = 0; mi < 4; mi++) {
#pragma unroll
        for (int ni = 0; ni < 4; ni++) {
            const int col = cbase + ni * 8;
            const float bz0 = bias[col], bz1 = bias[col + 1];
            const int r0 = rbase + mi * 16;
            float2 o0; o0.x = acc[mi][ni][0] + bz0; o0.y = acc[mi][ni][1] + bz1;
            float2 o1; o1.x = acc[mi][ni][2] + bz0; o1.y = acc[mi][ni][3] + bz1;
            *(float2*)(C + (ull)r0 * N + col) = o0;
            *(float2*)(C + (ull)(r0 + 8) * N + col) = o1;
        }
    }
}

// ----------------------------------------------------------------------------
// Causal flash attention (fp32 f32x2), writes hi/lo bf16 for the out GEMM.
// ----------------------------------------------------------------------------
#define LDQ 65
#define ATTN_SMEM ((128 * LDQ + 64 * 32 + 32 * 64) * 4)

__global__ __launch_bounds__(128)
void attn_kernel()
{
    extern __shared__ __align__(16) float sh[];
    float* Qs = sh;                       // [128][65]
    float* Ks = sh + 128 * LDQ;           // [64][32]  d-major
    float* Vs = Ks + 64 * 32;             // [32][64]  j-major

    const int t  = threadIdx.x;
    const int qi = (int)gridDim.x - 1 - (int)blockIdx.x;
    const int bh = blockIdx.y;
    const int b  = bh >> 4;
    const int h  = bh & 15;

    const float* base = g_qkv + b * (S_ * H3) + h * (S_ * CH);
    const int r = qi * 128 + t;

    const float scale = rsqrtf(2048.0f);
    {
        const float* qrow = base + r * CH;
#pragma unroll
        for (int i = 0; i < 16; i++) {
            float4 v4 = *(const float4*)(qrow + i * 4);
            float* qd = Qs + t * LDQ + i * 4;
            qd[0] = v4.x * scale; qd[1] = v4.y * scale;
            qd[2] = v4.z * scale; qd[3] = v4.w * scale;
        }
    }

    ull o2[32];
#pragma unroll
    for (int i = 0; i < 32; i++) o2[i] = 0ull;
    float m = -1e30f, l = 0.0f;

    const int nkt = 4 * (qi + 1);
    const int jj = t >> 2;
    const int dbase = (t & 3) * 16;

    for (int kt = 0; kt < nkt; kt++) {
        __syncthreads();
        {
            const float* kr = base + (kt * 32 + jj) * CH + 64 + dbase;
            const float* vr = kr + 64;
#pragma unroll
            for (int i = 0; i < 4; i++) {
                float4 kv = *(const float4*)(kr + i * 4);
                const int d = dbase + i * 4;
                Ks[(d + 0) * 32 + jj] = kv.x;
                Ks[(d + 1) * 32 + jj] = kv.y;
                Ks[(d + 2) * 32 + jj] = kv.z;
                Ks[(d + 3) * 32 + jj] = kv.w;
                float4 vv = *(const float4*)(vr + i * 4);
                *(float4*)&Vs[jj * 64 + d] = vv;
            }
        }
        __syncthreads();

        ull s2[16];
#pragma unroll
        for (int i = 0; i < 16; i++) s2[i] = 0ull;
        const float* qrowS = Qs + t * LDQ;
#pragma unroll 4
        for (int d = 0; d < 64; d++) {
            ull qq = bcast2(qrowS[d]);
            const ulonglong2* kp = (const ulonglong2*)(Ks + d * 32);
#pragma unroll
            for (int j4 = 0; j4 < 8; j4++) {
                ulonglong2 kk = kp[j4];
                fma2(s2[2 * j4],     qq, kk.x);
                fma2(s2[2 * j4 + 1], qq, kk.y);
            }
        }

        float sv[32];
#pragma unroll
        for (int i = 0; i < 16; i++) unpack2(s2[i], sv[2 * i], sv[2 * i + 1]);
        const int colBase = kt * 32;
        float tmax = -1e30f;
#pragma unroll
        for (int j = 0; j < 32; j++) {
            if (colBase + j > r) sv[j] = -1e30f;
            tmax = fmaxf(tmax, sv[j]);
        }
        const float mnew = fmaxf(m, tmax);
        const float corr = __expf(m - mnew);
        m = mnew;
        float psum = 0.0f;
#pragma unroll
        for (int j = 0; j < 32; j++) {
            sv[j] = __expf(sv[j] - mnew);
            psum += sv[j];
        }
        l = l * corr + psum;
        ull cc = bcast2(corr);
#pragma unroll
        for (int i = 0; i < 32; i++) mul2(o2[i], o2[i], cc);

        for (int j = 0; j < 32; j++) {
            ull pp = bcast2(sv[j]);
            const ulonglong2* vp = (const ulonglong2*)(Vs + j * 64);
#pragma unroll
            for (int d4 = 0; d4 < 16; d4++) {
                ulonglong2 vv = vp[d4];
                fma2(o2[2 * d4],     pp, vv.x);
                fma2(o2[2 * d4 + 1], pp, vv.y);
            }
        }
    }

    // normalize, split hi/lo bf16, store to scrambled sa layout
    const float invl = 1.0f / l;
    ull ii = bcast2(invl);
#pragma unroll
    for (int i = 0; i < 32; i++) mul2(o2[i], o2[i], ii);

    __nv_bfloat16 hb[64], lb[64];
#pragma unroll
    for (int i = 0; i < 32; i++) {
        float x0, x1; unpack2(o2[i], x0, x1);
        __nv_bfloat16 h0 = __float2bfloat16(x0);
        __nv_bfloat16 h1 = __float2bfloat16(x1);
        hb[2 * i] = h0; hb[2 * i + 1] = h1;
        lb[2 * i]     = __float2bfloat16(x0 - __bfloat162float(h0));
        lb[2 * i + 1] = __float2bfloat16(x1 - __bfloat162float(h1));
    }
    const ull rowoff = (ull)(b * S_ + h * 128 + (r >> 4)) * E_ + (r & 15) * 64;
    __nv_bfloat16* dh = g_sah + rowoff;
    __nv_bfloat16* dl = g_sal + rowoff;
#pragma unroll
    for (int i = 0; i < 8; i++) {
        *(uint4*)(dh + i * 8) = ((uint4*)hb)[i];
        *(uint4*)(dl + i * 8) = ((uint4*)lb)[i];
    }
}

// ----------------------------------------------------------------------------
extern "C" void kernel_launch(void* const* d_in, const int* in_sizes, int n_in,
                              void* d_out, int out_size)
{
    const float* x     = (const float*)d_in[0];
    const float* W_qkv = (const float*)d_in[1];
    const float* b_qkv = (const float*)d_in[2];
    const float* W_out = (const float*)d_in[3];
    const float* b_out = (const float*)d_in[4];
    float* out = (float*)d_out;

    float* qkv = nullptr;
    __nv_bfloat16 *xh, *xl, *wqh, *wql, *woh, *wol, *sah, *sal;
    cudaGetSymbolAddress((void**)&qkv, g_qkv);
    cudaGetSymbolAddress((void**)&xh, g_xh);   cudaGetSymbolAddress((void**)&xl, g_xl);
    cudaGetSymbolAddress((void**)&wqh, g_wqh); cudaGetSymbolAddress((void**)&wql, g_wql);
    cudaGetSymbolAddress((void**)&woh, g_woh); cudaGetSymbolAddress((void**)&wol, g_wol);
    cudaGetSymbolAddress((void**)&sah, g_sah); cudaGetSymbolAddress((void**)&sal, g_sal);

    cudaFuncSetAttribute(attn_kernel,
                         cudaFuncAttributeMaxDynamicSharedMemorySize, ATTN_SMEM);

    // 0) operand prep
    {
        const int n4 = MROWS * E_ / 4;
        split_kernel<<<(n4 + 255) / 256, 256>>>(x, xh, xl, n4);
        transpose_split_kernel<<<dim3(H3 / 32, E_ / 32), dim3(32, 8)>>>(
            W_qkv, wqh, wql, E_, H3);
        transpose_split_kernel<<<dim3(E_ / 32, E_ / 32), dim3(32, 8)>>>(
            W_out, woh, wol, E_, E_);
    }

    // 1) QKV projection on HMMA: [8192,1024] @ [1024,3072] + b
    gemm_tc_kernel<<<dim3(H3 / GBN, MROWS / GBM), 256>>>(
        xh, xl, wqh, wql, b_qkv, qkv, MROWS, H3, E_);

    // 2) causal attention per (b,h), writes hi/lo bf16 sa
    attn_kernel<<<dim3(16, B_ * NH), 128, ATTN_SMEM>>>();

    // 3) output projection on HMMA: [8192,1024] @ [1024,1024] + b
    gemm_tc_kernel<<<dim3(E_ / GBN, MROWS / GBM), 256>>>(
        sah, sal, woh, wol, b_out, out, MROWS, E_, E_);
}

// round 9
// speedup vs baseline: 2.3648x; 1.9012x over previous
#include <cuda_runtime.h>
#include <cuda_bf16.h>
#include <cstdint>

// ----------------------------------------------------------------------------
// MaskedMSA: x@Wqkv+b -> (faithful reshape) -> causal MHA -> sa@Wout+b
// B=4, S=2048, E=1024, HIDDEN=1024, HEADS=16, d_head=64
// Everything heavy on HMMA (mma.sync m16n8k16 bf16) with hi/lo splits.
// ----------------------------------------------------------------------------

#define B_  4
#define S_  2048
#define E_  1024
#define H3  3072
#define NH  16
#define CH  192
#define MROWS (B_ * S_)   // 8192

typedef unsigned long long ull;

// ---------------- scratch (no cudaMalloc allowed) ----------------
__device__ __nv_bfloat16 g_qkvh[MROWS * H3];        // qkv hi/lo (GEMM1 output)
__device__ __nv_bfloat16 g_qkvl[MROWS * H3];
__device__ __nv_bfloat16 g_xh[MROWS * E_];          // x hi/lo
__device__ __nv_bfloat16 g_xl[MROWS * E_];
__device__ __nv_bfloat16 g_wqh[H3 * E_];            // W_qkv^T hi/lo
__device__ __nv_bfloat16 g_wql[H3 * E_];
__device__ __nv_bfloat16 g_woh[E_ * E_];            // W_out^T hi/lo
__device__ __nv_bfloat16 g_wol[E_ * E_];
__device__ __nv_bfloat16 g_sah[MROWS * E_];         // attention out hi/lo
__device__ __nv_bfloat16 g_sal[MROWS * E_];

// ---------------- helpers ----------------
__device__ __forceinline__ uint32_t s2u(const void* p) {
    uint32_t a;
    asm("{ .reg .u64 t; cvta.to.shared.u64 t, %1; cvt.u32.u64 %0, t; }" : "=r"(a) : "l"(p));
    return a;
}
__device__ __forceinline__ void ldm_x4(uint32_t* r, uint32_t addr) {
    asm volatile("ldmatrix.sync.aligned.m8n8.x4.shared.b16 {%0,%1,%2,%3}, [%4];"
                 : "=r"(r[0]), "=r"(r[1]), "=r"(r[2]), "=r"(r[3]) : "r"(addr));
}
__device__ __forceinline__ void ldm_x4_t(uint32_t* r, uint32_t addr) {
    asm volatile("ldmatrix.sync.aligned.m8n8.x4.trans.shared.b16 {%0,%1,%2,%3}, [%4];"
                 : "=r"(r[0]), "=r"(r[1]), "=r"(r[2]), "=r"(r[3]) : "r"(addr));
}
__device__ __forceinline__ void ldm_x2(uint32_t* r, uint32_t addr) {
    asm volatile("ldmatrix.sync.aligned.m8n8.x2.shared.b16 {%0,%1}, [%2];"
                 : "=r"(r[0]), "=r"(r[1]) : "r"(addr));
}
__device__ __forceinline__ void mma_bf16(float* d, const uint32_t* a, const uint32_t* b) {
    asm volatile("mma.sync.aligned.m16n8k16.row.col.f32.bf16.bf16.f32 "
                 "{%0,%1,%2,%3}, {%4,%5,%6,%7}, {%8,%9}, {%0,%1,%2,%3};"
                 : "+f"(d[0]), "+f"(d[1]), "+f"(d[2]), "+f"(d[3])
                 : "r"(a[0]), "r"(a[1]), "r"(a[2]), "r"(a[3]), "r"(b[0]), "r"(b[1]));
}
// pack (lo, hi) floats into bf16x2 (lo in bits[15:0])
__device__ __forceinline__ uint32_t packbf(float lo, float hi) {
    uint32_t r; asm("cvt.rn.bf16x2.f32 %0, %1, %2;" : "=r"(r) : "f"(hi), "f"(lo)); return r;
}
__device__ __forceinline__ void cp16(uint32_t dst, const void* src) {
    asm volatile("cp.async.ca.shared.global [%0], [%1], 16;" :: "r"(dst), "l"(src));
}
__device__ __forceinline__ void cp_commit() { asm volatile("cp.async.commit_group;" ::: "memory"); }
template <int N> __device__ __forceinline__ void cp_wait() {
    asm volatile("cp.async.wait_group %0;" :: "n"(N) : "memory");
}

// ----------------------------------------------------------------------------
// Conversion kernels
// ----------------------------------------------------------------------------
__global__ void split_kernel(const float* __restrict__ in,
                             __nv_bfloat16* __restrict__ hi,
                             __nv_bfloat16* __restrict__ lo, int n4) {
    int i = blockIdx.x * blockDim.x + threadIdx.x;
    if (i >= n4) return;
    float4 v = ((const float4*)in)[i];
    uint32_t h0 = packbf(v.x, v.y), h1 = packbf(v.z, v.w);
    float f0 = __uint_as_float(h0 << 16), f1 = __uint_as_float(h0 & 0xffff0000u);
    float f2 = __uint_as_float(h1 << 16), f3 = __uint_as_float(h1 & 0xffff0000u);
    uint32_t l0 = packbf(v.x - f0, v.y - f1), l1 = packbf(v.z - f2, v.w - f3);
    ((uint32_t*)hi)[2 * i] = h0; ((uint32_t*)hi)[2 * i + 1] = h1;
    ((uint32_t*)lo)[2 * i] = l0; ((uint32_t*)lo)[2 * i + 1] = l1;
}

// W [K,N] fp32 -> Th/Tl [N,K] bf16
__global__ void transpose_split_kernel(const float* __restrict__ W,
                                       __nv_bfloat16* __restrict__ Th,
                                       __nv_bfloat16* __restrict__ Tl,
                                       int K, int N) {
    __shared__ float tile[32][33];
    const int bx = blockIdx.x * 32, by = blockIdx.y * 32;
    const int tx = threadIdx.x, ty = threadIdx.y;
#pragma unroll
    for (int i = 0; i < 32; i += 8)
        tile[ty + i][tx] = W[(by + ty + i) * N + bx + tx];
    __syncthreads();
#pragma unroll
    for (int i = 0; i < 32; i += 8) {
        float v = tile[tx][ty + i];
        __nv_bfloat16 h = __float2bfloat16(v);
        int idx = (bx + ty + i) * K + by + tx;
        Th[idx] = h;
        Tl[idx] = __float2bfloat16(v - __bfloat162float(h));
    }
}

// ----------------------------------------------------------------------------
// HMMA GEMM: C = Ah@Bh^T + Ah@Bl^T + Al@Bh^T + bias
// Output either fp32 C, or hi/lo bf16 (Ch/Cl) when Ch != nullptr.
// ----------------------------------------------------------------------------
#define GBM 128
#define GBN 128
#define GBK 32
#define LDT 40
#define TBUF (GBM * LDT)

__global__ __launch_bounds__(256)
void gemm_tc_kernel(const __nv_bfloat16* __restrict__ Ah, const __nv_bfloat16* __restrict__ Al,
                    const __nv_bfloat16* __restrict__ Bh, const __nv_bfloat16* __restrict__ Bl,
                    const float* __restrict__ bias, float* __restrict__ C,
                    __nv_bfloat16* __restrict__ Ch, __nv_bfloat16* __restrict__ Cl,
                    int M, int N, int K)
{
    __shared__ __align__(16) __nv_bfloat16 sA[2 * TBUF];
    __shared__ __align__(16) __nv_bfloat16 sB[2 * TBUF];

    const int t = threadIdx.x;
    const int lane = t & 31;
    const int warp = t >> 5;
    const int wm = warp & 1, wn = warp >> 1;
    const int bm = blockIdx.y * GBM, bn = blockIdx.x * GBN;

    const int lrow = t >> 1;
    const int lhalf = (t & 1) * 16;

    const uint32_t sAu = s2u(sA);
    const uint32_t sBu = s2u(sB);

    const uint32_t aoff = ((uint32_t)(wm * 64 + (lane & 15)) * LDT + (lane >> 4) * 8) * 2;
    const uint32_t boff = ((uint32_t)(wn * 32 + (lane & 7)) * LDT + ((lane >> 3) & 1) * 8) * 2;

    float acc[4][4][4];
#pragma unroll
    for (int mi = 0; mi < 4; mi++)
#pragma unroll
        for (int ni = 0; ni < 4; ni++)
#pragma unroll
            for (int j = 0; j < 4; j++) acc[mi][ni][j] = 0.0f;

    const int nkt = K / GBK;
    const int ntile = 3 * nkt;

    auto aptr = [&](int tl) -> const uint4* {
        const int seg = tl / nkt, kt = tl % nkt;
        const __nv_bfloat16* A = (seg == 2) ? Al : Ah;
        return (const uint4*)(A + (ull)(bm + lrow) * K + kt * GBK + lhalf);
    };
    auto bptr = [&](int tl) -> const uint4* {
        const int seg = tl / nkt, kt = tl % nkt;
        const __nv_bfloat16* Bw = (seg == 1) ? Bl : Bh;
        return (const uint4*)(Bw + (ull)(bn + lrow) * K + kt * GBK + lhalf);
    };

    uint4 pa0, pa1, pb0, pb1;
    { const uint4* p = aptr(0); pa0 = p[0]; pa1 = p[1]; }
    { const uint4* p = bptr(0); pb0 = p[0]; pb1 = p[1]; }

    __nv_bfloat16* stA = sA + lrow * LDT + lhalf;
    __nv_bfloat16* stB = sB + lrow * LDT + lhalf;

    *(uint4*)stA = pa0; *(uint4*)(stA + 8) = pa1;
    *(uint4*)stB = pb0; *(uint4*)(stB + 8) = pb1;
    __syncthreads();

    for (int tl = 0; tl < ntile; tl++) {
        const int cur = tl & 1;
        const int nxt = cur ^ 1;

        if (tl + 1 < ntile) {
            const uint4* p = aptr(tl + 1); pa0 = p[0]; pa1 = p[1];
            const uint4* q = bptr(tl + 1); pb0 = q[0]; pb1 = q[1];
        }

        const uint32_t aB = sAu + cur * (TBUF * 2) + aoff;
        const uint32_t bB = sBu + cur * (TBUF * 2) + boff;
#pragma unroll
        for (int ks = 0; ks < 2; ks++) {
            uint32_t af[4][4], bf[4][2];
#pragma unroll
            for (int mi = 0; mi < 4; mi++)
                ldm_x4(af[mi], aB + ((uint32_t)mi * 16 * LDT + ks * 16) * 2);
#pragma unroll
            for (int ni = 0; ni < 4; ni++)
                ldm_x2(bf[ni], bB + ((uint32_t)ni * 8 * LDT + ks * 16) * 2);
#pragma unroll
            for (int mi = 0; mi < 4; mi++)
#pragma unroll
                for (int ni = 0; ni < 4; ni++)
                    mma_bf16(acc[mi][ni], af[mi], bf[ni]);
        }

        if (tl + 1 < ntile) {
            __nv_bfloat16* dA = stA + nxt * TBUF;
            __nv_bfloat16* dB = stB + nxt * TBUF;
            *(uint4*)dA = pa0; *(uint4*)(dA + 8) = pa1;
            *(uint4*)dB = pb0; *(uint4*)(dB + 8) = pb1;
        }
        __syncthreads();
    }

    const int rbase = bm + wm * 64 + (lane >> 2);
    const int cbase = bn + wn * 32 + (lane & 3) * 2;
#pragma unroll
    for (int mi = 0; mi < 4; mi++) {
#pragma unroll
        for (int ni = 0; ni < 4; ni++) {
            const int col = cbase + ni * 8;
            const float bz0 = bias[col], bz1 = bias[col + 1];
            const int r0 = rbase + mi * 16;
            float o00 = acc[mi][ni][0] + bz0, o01 = acc[mi][ni][1] + bz1;
            float o10 = acc[mi][ni][2] + bz0, o11 = acc[mi][ni][3] + bz1;
            if (Ch) {
                uint32_t h0 = packbf(o00, o01);
                uint32_t h1 = packbf(o10, o11);
                float f00 = __uint_as_float(h0 << 16), f01 = __uint_as_float(h0 & 0xffff0000u);
                float f10 = __uint_as_float(h1 << 16), f11 = __uint_as_float(h1 & 0xffff0000u);
                uint32_t l0 = packbf(o00 - f00, o01 - f01);
                uint32_t l1 = packbf(o10 - f10, o11 - f11);
                *(uint32_t*)(Ch + (ull)r0 * N + col) = h0;
                *(uint32_t*)(Ch + (ull)(r0 + 8) * N + col) = h1;
                *(uint32_t*)(Cl + (ull)r0 * N + col) = l0;
                *(uint32_t*)(Cl + (ull)(r0 + 8) * N + col) = l1;
            } else {
                float2 a0; a0.x = o00; a0.y = o01;
                float2 a1; a1.x = o10; a1.y = o11;
                *(float2*)(C + (ull)r0 * N + col) = a0;
                *(float2*)(C + (ull)(r0 + 8) * N + col) = a1;
            }
        }
    }
}

// ----------------------------------------------------------------------------
// HMMA causal flash attention.
// 256 threads / 8 warps; 128 q-rows per CTA (16 per warp); KT=64 K-columns per
// iteration; cp.async double-buffered {Kh,Kl,Vh,Vl}; 2-pass QK, 3-pass PV.
// Writes hi/lo bf16 sa in the scrambled layout.
// ----------------------------------------------------------------------------
#define LQ 72
#define QS_ELEMS (128 * LQ)
#define MAT_ELEMS (64 * LQ)
#define ATTN_SMEM ((QS_ELEMS + 2 * 4 * MAT_ELEMS) * 2)

__global__ __launch_bounds__(256)
void attn_kernel()
{
    extern __shared__ __align__(16) __nv_bfloat16 sm[];
    __nv_bfloat16* Qs = sm;
    __nv_bfloat16* KV = sm + QS_ELEMS;   // [buf][4][64*LQ]  (Kh,Kl,Vh,Vl)

    const int t = threadIdx.x, lane = t & 31, w = t >> 5;
    const int qi = 15 - (int)blockIdx.x;     // heavy tiles first
    const int bh = blockIdx.y, b = bh >> 4, h = bh & 15;
    const ull base = (ull)b * (S_ * H3) + (ull)h * (S_ * CH);
    const __nv_bfloat16* GH = g_qkvh + base;
    const __nv_bfloat16* GL = g_qkvl + base;
    const int qbase = qi * 128;

    // stage Q (hi only)
#pragma unroll
    for (int i = t; i < 128 * 8; i += 256) {
        int row = i >> 3, seg = i & 7;
        *(uint4*)(Qs + row * LQ + seg * 8) =
            *(const uint4*)(GH + (ull)(qbase + row) * CH + seg * 8);
    }

    const uint32_t kvB = s2u(KV);
    auto stage = [&](int kt, int buf) {
        const int j0 = kt * 64;
        const uint32_t dstb = kvB + buf * (4 * MAT_ELEMS * 2);
#pragma unroll
        for (int i = t; i < 4 * 64 * 8; i += 256) {
            int mmat = i >> 9;
            int row = (i >> 3) & 63;
            int seg = i & 7;
            const __nv_bfloat16* src = ((mmat & 1) ? GL : GH)
                + (ull)(j0 + row) * CH + ((mmat >= 2) ? 128 : 64) + seg * 8;
            cp16(dstb + (mmat * MAT_ELEMS + row * LQ + seg * 8) * 2, src);
        }
    };

    stage(0, 0); cp_commit();

    const int nkt = 2 * (qi + 1);
    const int r0g = qbase + w * 16 + (lane >> 2);
    const int r1g = r0g + 8;
    const float scale = 0.02209708691f;   // (2*1024)^-0.5

    float m0 = -1e30f, m1 = -1e30f, l0 = 0.0f, l1 = 0.0f;
    float co[8][4];
#pragma unroll
    for (int i = 0; i < 8; i++)
#pragma unroll
        for (int j = 0; j < 4; j++) co[i][j] = 0.0f;

    uint32_t qf[4][4];
    bool qloaded = false;
    const uint32_t qaddr0 = s2u(Qs) + ((uint32_t)(w * 16 + (lane & 15)) * LQ + (lane >> 4) * 8) * 2;

    for (int kt = 0; kt < nkt; kt++) {
        const int cur = kt & 1;
        if (kt + 1 < nkt) { stage(kt + 1, cur ^ 1); cp_commit(); cp_wait<1>(); }
        else cp_wait<0>();
        __syncthreads();

        if (!qloaded) {
#pragma unroll
            for (int ks = 0; ks < 4; ks++) ldm_x4(qf[ks], qaddr0 + ks * 32);
            qloaded = true;
        }

        const uint32_t bufb = kvB + cur * (4 * MAT_ELEMS * 2);
        const uint32_t KhB = bufb, KlB = bufb + MAT_ELEMS * 2;
        const uint32_t VhB = bufb + 2 * MAT_ELEMS * 2, VlB = bufb + 3 * MAT_ELEMS * 2;

        // ---- S = Qh @ (Kh + Kl)^T ----
        float cs[8][4];
#pragma unroll
        for (int i = 0; i < 8; i++)
#pragma unroll
            for (int j = 0; j < 4; j++) cs[i][j] = 0.0f;

        const uint32_t kfoff = ((uint32_t)((lane & 7) + ((lane >> 4) & 1) * 8) * LQ
                                + ((lane >> 3) & 1) * 8) * 2;
#pragma unroll
        for (int pass = 0; pass < 2; pass++) {
            const uint32_t Kb = (pass ? KlB : KhB) + kfoff;
#pragma unroll
            for (int ks = 0; ks < 4; ks++) {
#pragma unroll
                for (int nip = 0; nip < 4; nip++) {
                    uint32_t bfr[4];
                    ldm_x4(bfr, Kb + ((uint32_t)nip * 16 * LQ + ks * 16) * 2);
                    mma_bf16(cs[2 * nip],     qf[ks], bfr);
                    mma_bf16(cs[2 * nip + 1], qf[ks], bfr + 2);
                }
            }
        }

        // ---- mask + scale + online softmax ----
        const int cb = kt * 64 + 2 * (lane & 3);
        float sv0[16], sv1[16];
        float tm0 = -1e30f, tm1 = -1e30f;
#pragma unroll
        for (int ni = 0; ni < 8; ni++) {
#pragma unroll
            for (int e = 0; e < 2; e++) {
                const int col = cb + ni * 8 + e;
                float v0 = (col <= r0g) ? cs[ni][e]     * scale : -1e30f;
                float v1 = (col <= r1g) ? cs[ni][2 + e] * scale : -1e30f;
                sv0[ni * 2 + e] = v0; sv1[ni * 2 + e] = v1;
                tm0 = fmaxf(tm0, v0); tm1 = fmaxf(tm1, v1);
            }
        }
        tm0 = fmaxf(tm0, __shfl_xor_sync(0xffffffffu, tm0, 1));
        tm0 = fmaxf(tm0, __shfl_xor_sync(0xffffffffu, tm0, 2));
        tm1 = fmaxf(tm1, __shfl_xor_sync(0xffffffffu, tm1, 1));
        tm1 = fmaxf(tm1, __shfl_xor_sync(0xffffffffu, tm1, 2));
        const float mn0 = fmaxf(m0, tm0), mn1 = fmaxf(m1, tm1);
        const float corr0 = __expf(m0 - mn0), corr1 = __expf(m1 - mn1);
        m0 = mn0; m1 = mn1;
        float ps0 = 0.0f, ps1 = 0.0f;
#pragma unroll
        for (int i = 0; i < 16; i++) {
            sv0[i] = __expf(sv0[i] - mn0); ps0 += sv0[i];
            sv1[i] = __expf(sv1[i] - mn1); ps1 += sv1[i];
        }
        ps0 += __shfl_xor_sync(0xffffffffu, ps0, 1);
        ps0 += __shfl_xor_sync(0xffffffffu, ps0, 2);
        ps1 += __shfl_xor_sync(0xffffffffu, ps1, 1);
        ps1 += __shfl_xor_sync(0xffffffffu, ps1, 2);
        l0 = l0 * corr0 + ps0;
        l1 = l1 * corr1 + ps1;
#pragma unroll
        for (int nd = 0; nd < 8; nd++) {
            co[nd][0] *= corr0; co[nd][1] *= corr0;
            co[nd][2] *= corr1; co[nd][3] *= corr1;
        }

        // ---- P hi/lo A-fragments straight from S fragments ----
        uint32_t ph[4][4], pl[4][4];
#pragma unroll
        for (int kj = 0; kj < 4; kj++) {
            uint32_t a0 = packbf(sv0[4 * kj],     sv0[4 * kj + 1]);
            uint32_t a1 = packbf(sv1[4 * kj],     sv1[4 * kj + 1]);
            uint32_t a2 = packbf(sv0[4 * kj + 2], sv0[4 * kj + 3]);
            uint32_t a3 = packbf(sv1[4 * kj + 2], sv1[4 * kj + 3]);
            ph[kj][0] = a0; ph[kj][1] = a1; ph[kj][2] = a2; ph[kj][3] = a3;
            pl[kj][0] = packbf(sv0[4 * kj]     - __uint_as_float(a0 << 16),
                               sv0[4 * kj + 1] - __uint_as_float(a0 & 0xffff0000u));
            pl[kj][1] = packbf(sv1[4 * kj]     - __uint_as_float(a1 << 16),
                               sv1[4 * kj + 1] - __uint_as_float(a1 & 0xffff0000u));
            pl[kj][2] = packbf(sv0[4 * kj + 2] - __uint_as_float(a2 << 16),
                               sv0[4 * kj + 3] - __uint_as_float(a2 & 0xffff0000u));
            pl[kj][3] = packbf(sv1[4 * kj + 2] - __uint_as_float(a3 << 16),
                               sv1[4 * kj + 3] - __uint_as_float(a3 & 0xffff0000u));
        }

        // ---- O += Ph@Vh + Ph@Vl + Pl@Vh ----
        const uint32_t vfoff = ((uint32_t)(lane & 15) * LQ) * 2 + (lane >> 4) * 16;
#pragma unroll
        for (int pass = 0; pass < 3; pass++) {
            const uint32_t Vb = ((pass == 1) ? VlB : VhB) + vfoff;
            const uint32_t (*pa)[4] = (pass == 2) ? pl : ph;
#pragma unroll
            for (int kj = 0; kj < 4; kj++) {
#pragma unroll
                for (int ndp = 0; ndp < 4; ndp++) {
                    uint32_t bfr[4];
                    ldm_x4_t(bfr, Vb + (uint32_t)kj * 16 * LQ * 2 + ndp * 32);
                    mma_bf16(co[2 * ndp],     pa[kj], bfr);
                    mma_bf16(co[2 * ndp + 1], pa[kj], bfr + 2);
                }
            }
        }
        __syncthreads();
    }

    // ---- normalize, split hi/lo, store to scrambled sa layout ----
    const float il0 = 1.0f / l0, il1 = 1.0f / l1;
    const ull row0 = (ull)(b * S_ + h * 128 + (r0g >> 4)) * E_ + (r0g & 15) * 64;
    const ull row1 = (ull)(b * S_ + h * 128 + (r1g >> 4)) * E_ + (r1g & 15) * 64;
    const int dcol = 2 * (lane & 3);
#pragma unroll
    for (int nd = 0; nd < 8; nd++) {
        const int d = nd * 8 + dcol;
        float o00 = co[nd][0] * il0, o01 = co[nd][1] * il0;
        float o10 = co[nd][2] * il1, o11 = co[nd][3] * il1;
        uint32_t h0 = packbf(o00, o01);
        uint32_t h1 = packbf(o10, o11);
        uint32_t q0 = packbf(o00 - __uint_as_float(h0 << 16),
                             o01 - __uint_as_float(h0 & 0xffff0000u));
        uint32_t q1 = packbf(o10 - __uint_as_float(h1 << 16),
                             o11 - __uint_as_float(h1 & 0xffff0000u));
        *(uint32_t*)(g_sah + row0 + d) = h0;
        *(uint32_t*)(g_sah + row1 + d) = h1;
        *(uint32_t*)(g_sal + row0 + d) = q0;
        *(uint32_t*)(g_sal + row1 + d) = q1;
    }
}

// ----------------------------------------------------------------------------
extern "C" void kernel_launch(void* const* d_in, const int* in_sizes, int n_in,
                              void* d_out, int out_size)
{
    const float* x     = (const float*)d_in[0];
    const float* W_qkv = (const float*)d_in[1];
    const float* b_qkv = (const float*)d_in[2];
    const float* W_out = (const float*)d_in[3];
    const float* b_out = (const float*)d_in[4];
    float* out = (float*)d_out;

    __nv_bfloat16 *qh, *ql, *xh, *xl, *wqh, *wql, *woh, *wol, *sah, *sal;
    cudaGetSymbolAddress((void**)&qh, g_qkvh); cudaGetSymbolAddress((void**)&ql, g_qkvl);
    cudaGetSymbolAddress((void**)&xh, g_xh);   cudaGetSymbolAddress((void**)&xl, g_xl);
    cudaGetSymbolAddress((void**)&wqh, g_wqh); cudaGetSymbolAddress((void**)&wql, g_wql);
    cudaGetSymbolAddress((void**)&woh, g_woh); cudaGetSymbolAddress((void**)&wol, g_wol);
    cudaGetSymbolAddress((void**)&sah, g_sah); cudaGetSymbolAddress((void**)&sal, g_sal);

    cudaFuncSetAttribute(attn_kernel,
                         cudaFuncAttributeMaxDynamicSharedMemorySize, ATTN_SMEM);

    // 0) operand prep
    {
        const int n4 = MROWS * E_ / 4;
        split_kernel<<<(n4 + 255) / 256, 256>>>(x, xh, xl, n4);
        transpose_split_kernel<<<dim3(H3 / 32, E_ / 32), dim3(32, 8)>>>(
            W_qkv, wqh, wql, E_, H3);
        transpose_split_kernel<<<dim3(E_ / 32, E_ / 32), dim3(32, 8)>>>(
            W_out, woh, wol, E_, E_);
    }

    // 1) QKV projection -> hi/lo bf16 qkv
    gemm_tc_kernel<<<dim3(H3 / GBN, MROWS / GBM), 256>>>(
        xh, xl, wqh, wql, b_qkv, nullptr, qh, ql, MROWS, H3, E_);

    // 2) HMMA causal attention -> hi/lo bf16 sa
    attn_kernel<<<dim3(16, B_ * NH), 256, ATTN_SMEM>>>();

    // 3) output projection -> fp32 out
    gemm_tc_kernel<<<dim3(E_ / GBN, MROWS / GBM), 256>>>(
        sah, sal, woh, wol, b_out, out, nullptr, nullptr, MROWS, E_, E_);
}

// round 10
// speedup vs baseline: 3.1482x; 1.3313x over previous
#include <cuda_runtime.h>
#include <cuda_bf16.h>
#include <cstdint>

// ----------------------------------------------------------------------------
// MaskedMSA: x@Wqkv+b -> (faithful reshape) -> causal MHA -> sa@Wout+b
// B=4, S=2048, E=1024, HIDDEN=1024, HEADS=16, d_head=64
// HMMA everywhere; GEMMs use fused 3-term hi/lo bf16 (Ah·Bh + Al·Bh + Ah·Bl)
// with single staging of all 4 tiles per k-step + XOR-swizzled SMEM.
// ----------------------------------------------------------------------------

#define B_  4
#define S_  2048
#define E_  1024
#define H3  3072
#define NH  16
#define CH  192
#define MROWS (B_ * S_)   // 8192

typedef unsigned long long ull;

// ---------------- scratch (no cudaMalloc allowed) ----------------
__device__ __nv_bfloat16 g_qkvh[MROWS * H3];
__device__ __nv_bfloat16 g_qkvl[MROWS * H3];
__device__ __nv_bfloat16 g_xh[MROWS * E_];
__device__ __nv_bfloat16 g_xl[MROWS * E_];
__device__ __nv_bfloat16 g_wqh[H3 * E_];
__device__ __nv_bfloat16 g_wql[H3 * E_];
__device__ __nv_bfloat16 g_woh[E_ * E_];
__device__ __nv_bfloat16 g_wol[E_ * E_];
__device__ __nv_bfloat16 g_sah[MROWS * E_];
__device__ __nv_bfloat16 g_sal[MROWS * E_];

// ---------------- helpers ----------------
__device__ __forceinline__ uint32_t s2u(const void* p) {
    uint32_t a;
    asm("{ .reg .u64 t; cvta.to.shared.u64 t, %1; cvt.u32.u64 %0, t; }" : "=r"(a) : "l"(p));
    return a;
}
__device__ __forceinline__ void ldm_x4(uint32_t* r, uint32_t addr) {
    asm volatile("ldmatrix.sync.aligned.m8n8.x4.shared.b16 {%0,%1,%2,%3}, [%4];"
                 : "=r"(r[0]), "=r"(r[1]), "=r"(r[2]), "=r"(r[3]) : "r"(addr));
}
__device__ __forceinline__ void ldm_x4_t(uint32_t* r, uint32_t addr) {
    asm volatile("ldmatrix.sync.aligned.m8n8.x4.trans.shared.b16 {%0,%1,%2,%3}, [%4];"
                 : "=r"(r[0]), "=r"(r[1]), "=r"(r[2]), "=r"(r[3]) : "r"(addr));
}
__device__ __forceinline__ void mma_bf16(float* d, const uint32_t* a, const uint32_t* b) {
    asm volatile("mma.sync.aligned.m16n8k16.row.col.f32.bf16.bf16.f32 "
                 "{%0,%1,%2,%3}, {%4,%5,%6,%7}, {%8,%9}, {%0,%1,%2,%3};"
                 : "+f"(d[0]), "+f"(d[1]), "+f"(d[2]), "+f"(d[3])
                 : "r"(a[0]), "r"(a[1]), "r"(a[2]), "r"(a[3]), "r"(b[0]), "r"(b[1]));
}
__device__ __forceinline__ uint32_t packbf(float lo, float hi) {
    uint32_t r; asm("cvt.rn.bf16x2.f32 %0, %1, %2;" : "=r"(r) : "f"(hi), "f"(lo)); return r;
}
__device__ __forceinline__ void cp16(uint32_t dst, const void* src) {
    asm volatile("cp.async.ca.shared.global [%0], [%1], 16;" :: "r"(dst), "l"(src));
}
__device__ __forceinline__ void cp_commit() { asm volatile("cp.async.commit_group;" ::: "memory"); }
template <int N> __device__ __forceinline__ void cp_wait() {
    asm volatile("cp.async.wait_group %0;" :: "n"(N) : "memory");
}

// ----------------------------------------------------------------------------
// Conversion kernels
// ----------------------------------------------------------------------------
__global__ void split_kernel(const float* __restrict__ in,
                             __nv_bfloat16* __restrict__ hi,
                             __nv_bfloat16* __restrict__ lo, int n4) {
    int i = blockIdx.x * blockDim.x + threadIdx.x;
    if (i >= n4) return;
    float4 v = ((const float4*)in)[i];
    uint32_t h0 = packbf(v.x, v.y), h1 = packbf(v.z, v.w);
    float f0 = __uint_as_float(h0 << 16), f1 = __uint_as_float(h0 & 0xffff0000u);
    float f2 = __uint_as_float(h1 << 16), f3 = __uint_as_float(h1 & 0xffff0000u);
    uint32_t l0 = packbf(v.x - f0, v.y - f1), l1 = packbf(v.z - f2, v.w - f3);
    ((uint32_t*)hi)[2 * i] = h0; ((uint32_t*)hi)[2 * i + 1] = h1;
    ((uint32_t*)lo)[2 * i] = l0; ((uint32_t*)lo)[2 * i + 1] = l1;
}

__global__ void transpose_split_kernel(const float* __restrict__ W,
                                       __nv_bfloat16* __restrict__ Th,
                                       __nv_bfloat16* __restrict__ Tl,
                                       int K, int N) {
    __shared__ float tile[32][33];
    const int bx = blockIdx.x * 32, by = blockIdx.y * 32;
    const int tx = threadIdx.x, ty = threadIdx.y;
#pragma unroll
    for (int i = 0; i < 32; i += 8)
        tile[ty + i][tx] = W[(by + ty + i) * N + bx + tx];
    __syncthreads();
#pragma unroll
    for (int i = 0; i < 32; i += 8) {
        float v = tile[tx][ty + i];
        __nv_bfloat16 h = __float2bfloat16(v);
        int idx = (bx + ty + i) * K + by + tx;
        Th[idx] = h;
        Tl[idx] = __float2bfloat16(v - __bfloat162float(h));
    }
}

// ----------------------------------------------------------------------------
// Fused HMMA GEMM: C = Ah@Bh^T + Al@Bh^T + Ah@Bl^T + bias
// A*: [M,K] bf16 row-major.  B*: [N,K] bf16 row-major.  Output fp32 or hi/lo.
// 128x128x32 tile, 256 threads, XOR-swizzled unpadded SMEM, cp.async 2-buffer.
// SMEM layout per buffer: [Ah | Al | Bh | Bl], each 128x32 bf16 (8 KB).
// Swizzle: element (row, quad) stored at quad' = quad ^ ((row>>1)&3), 64B rows.
// ----------------------------------------------------------------------------
#define GBM 128
#define GBN 128
#define GBK 32
#define MATB 8192
#define BUFB (4 * MATB)
#define GSMEM (2 * BUFB)    // 64 KB

__global__ __launch_bounds__(256)
void gemm_tc_kernel(const __nv_bfloat16* __restrict__ Ah, const __nv_bfloat16* __restrict__ Al,
                    const __nv_bfloat16* __restrict__ Bh, const __nv_bfloat16* __restrict__ Bl,
                    const float* __restrict__ bias, float* __restrict__ C,
                    __nv_bfloat16* __restrict__ Ch, __nv_bfloat16* __restrict__ Cl,
                    int M, int N, int K)
{
    extern __shared__ __align__(16) char gsm[];
    const uint32_t sb = s2u(gsm);
    const int t = threadIdx.x, lane = t & 31, warp = t >> 5;
    const int wm = warp & 1, wn = warp >> 1;
    const int bm = blockIdx.y * GBM, bn = blockIdx.x * GBN;

    // staging map: slot = t (+256): row = slot>>2 (invariant f), quad = slot&3
    const int srow = t >> 2;
    const int squad = t & 3;
    const uint32_t sq = (uint32_t)(squad ^ ((srow >> 1) & 3));
    const __nv_bfloat16* gsrc[4] = {
        Ah + (ull)(bm + srow) * K + squad * 8,
        Al + (ull)(bm + srow) * K + squad * 8,
        Bh + (ull)(bn + srow) * K + squad * 8,
        Bl + (ull)(bn + srow) * K + squad * 8 };
    const uint32_t sdst = sb + (uint32_t)srow * 64 + sq * 16;

    auto stage = [&](int kt, int buf) {
        const uint32_t d0 = sdst + (uint32_t)buf * BUFB;
        const int ke = kt * GBK;
#pragma unroll
        for (int m = 0; m < 4; m++) {
            cp16(d0 + m * MATB,            gsrc[m] + ke);
            cp16(d0 + m * MATB + 64 * 64,  gsrc[m] + ke + (ull)64 * K);
        }
    };

    // fragment addressing (swizzled)
    const int rA = wm * 64 + (lane & 15);
    const uint32_t fA = (uint32_t)((rA >> 1) & 3);
    const int hA = lane >> 4;
    const int rB = wn * 32 + (lane & 7) + (lane >> 4) * 8;
    const uint32_t fB = (uint32_t)((rB >> 1) & 3);
    const int hB = (lane >> 3) & 1;

    float acc[4][4][4];
#pragma unroll
    for (int mi = 0; mi < 4; mi++)
#pragma unroll
        for (int ni = 0; ni < 4; ni++)
#pragma unroll
            for (int j = 0; j < 4; j++) acc[mi][ni][j] = 0.0f;

    stage(0, 0); cp_commit();
    const int nkt = K / GBK;

    for (int kt = 0; kt < nkt; kt++) {
        const int cur = kt & 1;
        if (kt + 1 < nkt) { stage(kt + 1, cur ^ 1); cp_commit(); cp_wait<1>(); }
        else cp_wait<0>();
        __syncthreads();

        const uint32_t bb = sb + (uint32_t)cur * BUFB;
#pragma unroll
        for (int ks = 0; ks < 2; ks++) {
            uint32_t ah[4][4], al[4][4], bh[2][4], bl[2][4];
            const uint32_t qa = (((uint32_t)(2 * ks + hA)) ^ fA) * 16;
            const uint32_t qb = (((uint32_t)(2 * ks + hB)) ^ fB) * 16;
            const uint32_t arow = bb + (uint32_t)rA * 64 + qa;
            const uint32_t brow = bb + 2 * MATB + (uint32_t)rB * 64 + qb;
#pragma unroll
            for (int mi = 0; mi < 4; mi++) {
                ldm_x4(ah[mi], arow + mi * 1024);
                ldm_x4(al[mi], arow + MATB + mi * 1024);
            }
#pragma unroll
            for (int np = 0; np < 2; np++) {
                ldm_x4(bh[np], brow + np * 1024);
                ldm_x4(bl[np], brow + MATB + np * 1024);
            }
            // sweep 1: Ah x Bh
#pragma unroll
            for (int mi = 0; mi < 4; mi++)
#pragma unroll
                for (int ni = 0; ni < 4; ni++)
                    mma_bf16(acc[mi][ni], ah[mi], &bh[ni >> 1][(ni & 1) * 2]);
            // sweep 2: Al x Bh
#pragma unroll
            for (int mi = 0; mi < 4; mi++)
#pragma unroll
                for (int ni = 0; ni < 4; ni++)
                    mma_bf16(acc[mi][ni], al[mi], &bh[ni >> 1][(ni & 1) * 2]);
            // sweep 3: Ah x Bl
#pragma unroll
            for (int mi = 0; mi < 4; mi++)
#pragma unroll
                for (int ni = 0; ni < 4; ni++)
                    mma_bf16(acc[mi][ni], ah[mi], &bl[ni >> 1][(ni & 1) * 2]);
        }
        __syncthreads();
    }

    // epilogue
    const int rbase = bm + wm * 64 + (lane >> 2);
    const int cbase = bn + wn * 32 + (lane & 3) * 2;
#pragma unroll
    for (int mi = 0; mi < 4; mi++) {
#pragma unroll
        for (int ni = 0; ni < 4; ni++) {
            const int col = cbase + ni * 8;
            const float bz0 = bias[col], bz1 = bias[col + 1];
            const int r0 = rbase + mi * 16;
            float o00 = acc[mi][ni][0] + bz0, o01 = acc[mi][ni][1] + bz1;
            float o10 = acc[mi][ni][2] + bz0, o11 = acc[mi][ni][3] + bz1;
            if (Ch) {
                uint32_t h0 = packbf(o00, o01);
                uint32_t h1 = packbf(o10, o11);
                float f00 = __uint_as_float(h0 << 16), f01 = __uint_as_float(h0 & 0xffff0000u);
                float f10 = __uint_as_float(h1 << 16), f11 = __uint_as_float(h1 & 0xffff0000u);
                uint32_t l0 = packbf(o00 - f00, o01 - f01);
                uint32_t l1 = packbf(o10 - f10, o11 - f11);
                *(uint32_t*)(Ch + (ull)r0 * N + col) = h0;
                *(uint32_t*)(Ch + (ull)(r0 + 8) * N + col) = h1;
                *(uint32_t*)(Cl + (ull)r0 * N + col) = l0;
                *(uint32_t*)(Cl + (ull)(r0 + 8) * N + col) = l1;
            } else {
                float2 a0; a0.x = o00; a0.y = o01;
                float2 a1; a1.x = o10; a1.y = o11;
                *(float2*)(C + (ull)r0 * N + col) = a0;
                *(float2*)(C + (ull)(r0 + 8) * N + col) = a1;
            }
        }
    }
}

// ----------------------------------------------------------------------------
// HMMA causal flash attention (unchanged from R8 — passing at ~280us).
// ----------------------------------------------------------------------------
#define LQ 72
#define QS_ELEMS (128 * LQ)
#define MAT_ELEMS (64 * LQ)
#define ATTN_SMEM ((QS_ELEMS + 2 * 4 * MAT_ELEMS) * 2)

__device__ __forceinline__ void ldm_x2(uint32_t* r, uint32_t addr) {
    asm volatile("ldmatrix.sync.aligned.m8n8.x2.shared.b16 {%0,%1}, [%2];"
                 : "=r"(r[0]), "=r"(r[1]) : "r"(addr));
}

__global__ __launch_bounds__(256)
void attn_kernel()
{
    extern __shared__ __align__(16) __nv_bfloat16 sm[];
    __nv_bfloat16* Qs = sm;
    __nv_bfloat16* KV = sm + QS_ELEMS;

    const int t = threadIdx.x, lane = t & 31, w = t >> 5;
    const int qi = 15 - (int)blockIdx.x;
    const int bh = blockIdx.y, b = bh >> 4, h = bh & 15;
    const ull base = (ull)b * (S_ * H3) + (ull)h * (S_ * CH);
    const __nv_bfloat16* GH = g_qkvh + base;
    const __nv_bfloat16* GL = g_qkvl + base;
    const int qbase = qi * 128;

#pragma unroll
    for (int i = t; i < 128 * 8; i += 256) {
        int row = i >> 3, seg = i & 7;
        *(uint4*)(Qs + row * LQ + seg * 8) =
            *(const uint4*)(GH + (ull)(qbase + row) * CH + seg * 8);
    }

    const uint32_t kvB = s2u(KV);
    auto stage = [&](int kt, int buf) {
        const int j0 = kt * 64;
        const uint32_t dstb = kvB + buf * (4 * MAT_ELEMS * 2);
#pragma unroll
        for (int i = t; i < 4 * 64 * 8; i += 256) {
            int mmat = i >> 9;
            int row = (i >> 3) & 63;
            int seg = i & 7;
            const __nv_bfloat16* src = ((mmat & 1) ? GL : GH)
                + (ull)(j0 + row) * CH + ((mmat >= 2) ? 128 : 64) + seg * 8;
            cp16(dstb + (mmat * MAT_ELEMS + row * LQ + seg * 8) * 2, src);
        }
    };

    stage(0, 0); cp_commit();

    const int nkt = 2 * (qi + 1);
    const int r0g = qbase + w * 16 + (lane >> 2);
    const int r1g = r0g + 8;
    const float scale = 0.02209708691f;

    float m0 = -1e30f, m1 = -1e30f, l0 = 0.0f, l1 = 0.0f;
    float co[8][4];
#pragma unroll
    for (int i = 0; i < 8; i++)
#pragma unroll
        for (int j = 0; j < 4; j++) co[i][j] = 0.0f;

    uint32_t qf[4][4];
    bool qloaded = false;
    const uint32_t qaddr0 = s2u(Qs) + ((uint32_t)(w * 16 + (lane & 15)) * LQ + (lane >> 4) * 8) * 2;

    for (int kt = 0; kt < nkt; kt++) {
        const int cur = kt & 1;
        if (kt + 1 < nkt) { stage(kt + 1, cur ^ 1); cp_commit(); cp_wait<1>(); }
        else cp_wait<0>();
        __syncthreads();

        if (!qloaded) {
#pragma unroll
            for (int ks = 0; ks < 4; ks++) ldm_x4(qf[ks], qaddr0 + ks * 32);
            qloaded = true;
        }

        const uint32_t bufb = kvB + cur * (4 * MAT_ELEMS * 2);
        const uint32_t KhB = bufb, KlB = bufb + MAT_ELEMS * 2;
        const uint32_t VhB = bufb + 2 * MAT_ELEMS * 2, VlB = bufb + 3 * MAT_ELEMS * 2;

        float cs[8][4];
#pragma unroll
        for (int i = 0; i < 8; i++)
#pragma unroll
            for (int j = 0; j < 4; j++) cs[i][j] = 0.0f;

        const uint32_t kfoff = ((uint32_t)((lane & 7) + ((lane >> 4) & 1) * 8) * LQ
                                + ((lane >> 3) & 1) * 8) * 2;
#pragma unroll
        for (int pass = 0; pass < 2; pass++) {
            const uint32_t Kb = (pass ? KlB : KhB) + kfoff;
#pragma unroll
            for (int ks = 0; ks < 4; ks++) {
#pragma unroll
                for (int nip = 0; nip < 4; nip++) {
                    uint32_t bfr[4];
                    ldm_x4(bfr, Kb + ((uint32_t)nip * 16 * LQ + ks * 16) * 2);
                    mma_bf16(cs[2 * nip],     qf[ks], bfr);
                    mma_bf16(cs[2 * nip + 1], qf[ks], bfr + 2);
                }
            }
        }

        const int cb = kt * 64 + 2 * (lane & 3);
        float sv0[16], sv1[16];
        float tm0 = -1e30f, tm1 = -1e30f;
#pragma unroll
        for (int ni = 0; ni < 8; ni++) {
#pragma unroll
            for (int e = 0; e < 2; e++) {
                const int col = cb + ni * 8 + e;
                float v0 = (col <= r0g) ? cs[ni][e]     * scale : -1e30f;
                float v1 = (col <= r1g) ? cs[ni][2 + e] * scale : -1e30f;
                sv0[ni * 2 + e] = v0; sv1[ni * 2 + e] = v1;
                tm0 = fmaxf(tm0, v0); tm1 = fmaxf(tm1, v1);
            }
        }
        tm0 = fmaxf(tm0, __shfl_xor_sync(0xffffffffu, tm0, 1));
        tm0 = fmaxf(tm0, __shfl_xor_sync(0xffffffffu, tm0, 2));
        tm1 = fmaxf(tm1, __shfl_xor_sync(0xffffffffu, tm1, 1));
        tm1 = fmaxf(tm1, __shfl_xor_sync(0xffffffffu, tm1, 2));
        const float mn0 = fmaxf(m0, tm0), mn1 = fmaxf(m1, tm1);
        const float corr0 = __expf(m0 - mn0), corr1 = __expf(m1 - mn1);
        m0 = mn0; m1 = mn1;
        float ps0 = 0.0f, ps1 = 0.0f;
#pragma unroll
        for (int i = 0; i < 16; i++) {
            sv0[i] = __expf(sv0[i] - mn0); ps0 += sv0[i];
            sv1[i] = __expf(sv1[i] - mn1); ps1 += sv1[i];
        }
        ps0 += __shfl_xor_sync(0xffffffffu, ps0, 1);
        ps0 += __shfl_xor_sync(0xffffffffu, ps0, 2);
        ps1 += __shfl_xor_sync(0xffffffffu, ps1, 1);
        ps1 += __shfl_xor_sync(0xffffffffu, ps1, 2);
        l0 = l0 * corr0 + ps0;
        l1 = l1 * corr1 + ps1;
#pragma unroll
        for (int nd = 0; nd < 8; nd++) {
            co[nd][0] *= corr0; co[nd][1] *= corr0;
            co[nd][2] *= corr1; co[nd][3] *= corr1;
        }

        uint32_t ph[4][4], pl[4][4];
#pragma unroll
        for (int kj = 0; kj < 4; kj++) {
            uint32_t a0 = packbf(sv0[4 * kj],     sv0[4 * kj + 1]);
            uint32_t a1 = packbf(sv1[4 * kj],     sv1[4 * kj + 1]);
            uint32_t a2 = packbf(sv0[4 * kj + 2], sv0[4 * kj + 3]);
            uint32_t a3 = packbf(sv1[4 * kj + 2], sv1[4 * kj + 3]);
            ph[kj][0] = a0; ph[kj][1] = a1; ph[kj][2] = a2; ph[kj][3] = a3;
            pl[kj][0] = packbf(sv0[4 * kj]     - __uint_as_float(a0 << 16),
                               sv0[4 * kj + 1] - __uint_as_float(a0 & 0xffff0000u));
            pl[kj][1] = packbf(sv1[4 * kj]     - __uint_as_float(a1 << 16),
                               sv1[4 * kj + 1] - __uint_as_float(a1 & 0xffff0000u));
            pl[kj][2] = packbf(sv0[4 * kj + 2] - __uint_as_float(a2 << 16),
                               sv0[4 * kj + 3] - __uint_as_float(a2 & 0xffff0000u));
            pl[kj][3] = packbf(sv1[4 * kj + 2] - __uint_as_float(a3 << 16),
                               sv1[4 * kj + 3] - __uint_as_float(a3 & 0xffff0000u));
        }

        const uint32_t vfoff = ((uint32_t)(lane & 15) * LQ) * 2 + (lane >> 4) * 16;
#pragma unroll
        for (int pass = 0; pass < 3; pass++) {
            const uint32_t Vb = ((pass == 1) ? VlB : VhB) + vfoff;
            const uint32_t (*pa)[4] = (pass == 2) ? pl : ph;
#pragma unroll
            for (int kj = 0; kj < 4; kj++) {
#pragma unroll
                for (int ndp = 0; ndp < 4; ndp++) {
                    uint32_t bfr[4];
                    ldm_x4_t(bfr, Vb + (uint32_t)kj * 16 * LQ * 2 + ndp * 32);
                    mma_bf16(co[2 * ndp],     pa[kj], bfr);
                    mma_bf16(co[2 * ndp + 1], pa[kj], bfr + 2);
                }
            }
        }
        __syncthreads();
    }

    const float il0 = 1.0f / l0, il1 = 1.0f / l1;
    const ull row0 = (ull)(b * S_ + h * 128 + (r0g >> 4)) * E_ + (r0g & 15) * 64;
    const ull row1 = (ull)(b * S_ + h * 128 + (r1g >> 4)) * E_ + (r1g & 15) * 64;
    const int dcol = 2 * (lane & 3);
#pragma unroll
    for (int nd = 0; nd < 8; nd++) {
        const int d = nd * 8 + dcol;
        float o00 = co[nd][0] * il0, o01 = co[nd][1] * il0;
        float o10 = co[nd][2] * il1, o11 = co[nd][3] * il1;
        uint32_t h0 = packbf(o00, o01);
        uint32_t h1 = packbf(o10, o11);
        uint32_t q0 = packbf(o00 - __uint_as_float(h0 << 16),
                             o01 - __uint_as_float(h0 & 0xffff0000u));
        uint32_t q1 = packbf(o10 - __uint_as_float(h1 << 16),
                             o11 - __uint_as_float(h1 & 0xffff0000u));
        *(uint32_t*)(g_sah + row0 + d) = h0;
        *(uint32_t*)(g_sah + row1 + d) = h1;
        *(uint32_t*)(g_sal + row0 + d) = q0;
        *(uint32_t*)(g_sal + row1 + d) = q1;
    }
}

// ----------------------------------------------------------------------------
extern "C" void kernel_launch(void* const* d_in, const int* in_sizes, int n_in,
                              void* d_out, int out_size)
{
    const float* x     = (const float*)d_in[0];
    const float* W_qkv = (const float*)d_in[1];
    const float* b_qkv = (const float*)d_in[2];
    const float* W_out = (const float*)d_in[3];
    const float* b_out = (const float*)d_in[4];
    float* out = (float*)d_out;

    __nv_bfloat16 *qh, *ql, *xh, *xl, *wqh, *wql, *woh, *wol, *sah, *sal;
    cudaGetSymbolAddress((void**)&qh, g_qkvh); cudaGetSymbolAddress((void**)&ql, g_qkvl);
    cudaGetSymbolAddress((void**)&xh, g_xh);   cudaGetSymbolAddress((void**)&xl, g_xl);
    cudaGetSymbolAddress((void**)&wqh, g_wqh); cudaGetSymbolAddress((void**)&wql, g_wql);
    cudaGetSymbolAddress((void**)&woh, g_woh); cudaGetSymbolAddress((void**)&wol, g_wol);
    cudaGetSymbolAddress((void**)&sah, g_sah); cudaGetSymbolAddress((void**)&sal, g_sal);

    cudaFuncSetAttribute(attn_kernel,
                         cudaFuncAttributeMaxDynamicSharedMemorySize, ATTN_SMEM);
    cudaFuncSetAttribute(gemm_tc_kernel,
                         cudaFuncAttributeMaxDynamicSharedMemorySize, GSMEM);

    // 0) operand prep
    {
        const int n4 = MROWS * E_ / 4;
        split_kernel<<<(n4 + 255) / 256, 256>>>(x, xh, xl, n4);
        transpose_split_kernel<<<dim3(H3 / 32, E_ / 32), dim3(32, 8)>>>(
            W_qkv, wqh, wql, E_, H3);
        transpose_split_kernel<<<dim3(E_ / 32, E_ / 32), dim3(32, 8)>>>(
            W_out, woh, wol, E_, E_);
    }

    // 1) QKV projection -> hi/lo bf16 qkv
    gemm_tc_kernel<<<dim3(H3 / GBN, MROWS / GBM), 256, GSMEM>>>(
        xh, xl, wqh, wql, b_qkv, nullptr, qh, ql, MROWS, H3, E_);

    // 2) HMMA causal attention -> hi/lo bf16 sa
    attn_kernel<<<dim3(16, B_ * NH), 256, ATTN_SMEM>>>();

    // 3) output projection -> fp32 out
    gemm_tc_kernel<<<dim3(E_ / GBN, MROWS / GBM), 256, GSMEM>>>(
        sah, sal, woh, wol, b_out, out, nullptr, nullptr, MROWS, E_, E_);
}